// round 10
// baseline (speedup 1.0000x reference)
#include <cuda_runtime.h>
#include <stdint.h>

#define COLS   16384
#define TPB    512
#define NW     (TPB / 32)
#define V4     (COLS / 4 / TPB)   // 8 float4 per thread
#define CAP    2048
#define EQ_CAP 128
#define ANCHOR 129                // coarse bin d = clamp(ANCHOR - exp, 0, 7)

struct __align__(16) SmemT {
    union {
        unsigned long long cand[CAP];     // fast path: (bits<<32)|idx
        unsigned           hist[NW][256]; // fallback: per-warp hists
    } u;                                  // 16 KB
    unsigned tot[256];                    // refinement / merged histogram
    unsigned wtot[NW][8];                 // coarse per-warp totals
    int      eqIdx[EQ_CAP];
    unsigned prefix;
    int      r;
    int      eqCount;
    int      candCount;
    int      cutoff;
    int      fb;                          // fallback flag
    int      startLev;
};

// ---- legacy helpers (warp0 256-bin suffix select; match-aggregated hist) ----
__device__ __forceinline__ void hist_add(unsigned* h, unsigned d) {
    unsigned mm = __match_any_sync(0xffffffffu, d);
    if (d < 256u) {
        unsigned leader = __ffs(mm) - 1u;
        if ((threadIdx.x & 31u) == leader) h[d] += (unsigned)__popc(mm);
    }
}

__device__ __forceinline__ void select_bin(SmemT* s, int shift) {
    const int lane = threadIdx.x & 31;
    const unsigned r = (unsigned)s->r;
    const unsigned base = (unsigned)lane * 8u;
    unsigned loc[8];
    unsigned sum = 0;
#pragma unroll
    for (int j = 7; j >= 0; j--) { sum += s->tot[base + j]; loc[j] = sum; }
    const unsigned lanesum = sum;
    unsigned acc = lanesum;
#pragma unroll
    for (int o = 1; o < 32; o <<= 1) {
        unsigned v = __shfl_down_sync(0xffffffffu, acc, o);
        if (lane < 32 - o) acc += v;
    }
    const unsigned above = acc - lanesum;
#pragma unroll
    for (int j = 0; j < 8; j++) {
        unsigned g     = above + loc[j];
        unsigned gnext = (j == 7) ? above : (above + loc[j+1]);
        if (g >= r && gnext < r) {
            s->prefix |= (base + (unsigned)j) << shift;
            s->r = (int)(r - gnext);
        }
    }
}

__device__ __forceinline__ void bits_of(float4 v, unsigned bb[4]) {
    bb[0] = __float_as_uint(v.x);
    bb[1] = __float_as_uint(v.y);
    bb[2] = __float_as_uint(v.z);
    bb[3] = __float_as_uint(v.w);
}

__global__ void __launch_bounds__(TPB, 3)
topk_kernel(const float* __restrict__ x, const int* __restrict__ kptr,
            float* __restrict__ out)
{
    __shared__ SmemT s;
    const int tid  = threadIdx.x;
    const int w    = tid >> 5;
    const int lane = tid & 31;
    const size_t rowoff = (size_t)blockIdx.x * COLS;
    const float4* __restrict__ xin  = reinterpret_cast<const float4*>(x + rowoff);
    float4* __restrict__       xout = reinterpret_cast<float4*>(out + rowoff);
    float* __restrict__        orow = out + rowoff;

    const int k = *kptr;
    if (k >= COLS) {
#pragma unroll
        for (int i = 0; i < V4; i++) __stcs(&xout[i*TPB + tid], __ldcs(&xin[i*TPB + tid]));
        return;
    }
    if (k <= 0) {
        float4 z = make_float4(0.f, 0.f, 0.f, 0.f);
#pragma unroll
        for (int i = 0; i < V4; i++) __stcs(&xout[i*TPB + tid], z);
        return;
    }

    if (tid == 0) { s.candCount = 0; s.eqCount = 0; s.prefix = 0u; s.r = k; }
    __syncthreads();

    // ================= pass 1: single gmem read =================
    // coarse 8-bin register histogram + speculative compaction (d <= 1)
    unsigned clo = 0, chi = 0;              // 8 packed 8-bit counters
    const unsigned ltmask = (lane == 31) ? 0x7fffffffu : ((1u << lane) - 1u);
#pragma unroll
    for (int i = 0; i < V4; i++) {
        const int i4 = i * TPB + tid;
        float4 v = __ldcs(&xin[i4]);
        unsigned bb[4]; bits_of(v, bb);
#pragma unroll
        for (int j = 0; j < 4; j++) {
            int e = (int)((bb[j] >> 23) & 0xffu);
            int d = ANCHOR - e;
            d = (d < 0) ? 0 : (d > 7 ? 7 : d);
            unsigned inc = 1u << ((d & 3) << 3);
            if (d < 4) clo += inc; else chi += inc;
            // speculative candidate: top two coarse bins
            const bool c = (d <= 1);
            unsigned m = __ballot_sync(0xffffffffu, c);
            if (m) {
                const unsigned leader = __ffs(m) - 1u;
                int base = 0;
                if ((unsigned)lane == leader)
                    base = atomicAdd(&s.candCount, __popc(m));
                base = __shfl_sync(0xffffffffu, base, leader);
                if (c) {
                    int pos = base + __popc(m & ltmask);
                    if (pos < CAP)
                        s.u.cand[pos] = ((unsigned long long)bb[j] << 32)
                                        | (unsigned)(i4 * 4 + j);
                }
            }
        }
    }
    // warp-reduce packed counters (16-bit SIMD halves; max 1024/half, no carry)
    {
        unsigned a0 = clo & 0x00FF00FFu, a1 = (clo >> 8) & 0x00FF00FFu;
        unsigned a2 = chi & 0x00FF00FFu, a3 = (chi >> 8) & 0x00FF00FFu;
#pragma unroll
        for (int o = 16; o >= 1; o >>= 1) {
            a0 += __shfl_down_sync(0xffffffffu, a0, o);
            a1 += __shfl_down_sync(0xffffffffu, a1, o);
            a2 += __shfl_down_sync(0xffffffffu, a2, o);
            a3 += __shfl_down_sync(0xffffffffu, a3, o);
        }
        if (lane == 0) {
            s.wtot[w][0] = a0 & 0xffffu; s.wtot[w][2] = a0 >> 16;
            s.wtot[w][1] = a1 & 0xffffu; s.wtot[w][3] = a1 >> 16;
            s.wtot[w][4] = a2 & 0xffffu; s.wtot[w][6] = a2 >> 16;
            s.wtot[w][5] = a3 & 0xffffu; s.wtot[w][7] = a3 >> 16;
        }
    }
    __syncthreads();

    // ================= coarse select (warp 0, no extra barrier) =================
    if (w == 0) {
        unsigned cum = 0;
        if (lane < 8) {
#pragma unroll
            for (int ww = 0; ww < NW; ww++) cum += s.wtot[ww][lane];
        }
#pragma unroll
        for (int o = 1; o <= 4; o <<= 1) {     // inclusive scan lanes 0..7
            unsigned v = __shfl_up_sync(0xffffffffu, cum, o);
            if (lane >= (unsigned)o && lane < 8) cum += v;
        }
        unsigned c0  = __shfl_sync(0xffffffffu, cum, 0);
        unsigned ball = __ballot_sync(0xffffffffu, (lane < 8) && (cum >= (unsigned)k)) & 0xffu;
        int b = ball ? (int)(__ffs(ball) - 1) : 7;
        if (lane == 0) {
            bool fb = (b > 1) || (s.candCount > CAP);
            s.fb = fb ? 1 : 0;
            if (!fb) {
                if (b == 1) { s.prefix = (unsigned)(ANCHOR - 1) << 23;
                              s.r = k - (int)c0; s.startLev = 1; }
                else        { s.prefix = 0u; s.r = k; s.startLev = 0; }
            }
        }
    }
    __syncthreads();

    if (s.fb == 0) {
        // ================= FAST PATH =================
        const int cnt      = s.candCount;
        const int startLev = s.startLev;

        // refine: up to 4 levels of 8-bit radix over candidates (8+8+8+7)
#pragma unroll
        for (int lev = 0; lev < 4; lev++) {
            if (lev < startLev) continue;
            const int      shift = (lev == 0) ? 23 : (lev == 1) ? 15 : (lev == 2) ? 7 : 0;
            const int      hi    = (lev == 0) ? 31 : (lev == 1) ? 23 : (lev == 2) ? 15 : 7;
            const unsigned mask  = (lev == 3) ? 0x7fu : 0xffu;
            const unsigned pref_hi = s.prefix >> hi;

            if (tid < 256) s.tot[tid] = 0u;
            __syncthreads();
            for (int i = tid; i < cnt; i += TPB) {
                unsigned key = (unsigned)(s.u.cand[i] >> 32) & 0x7fffffffu;
                if ((key >> hi) == pref_hi)
                    atomicAdd(&s.tot[(key >> shift) & mask], 1u);
            }
            __syncthreads();
            if (tid < 32) select_bin(&s, shift);
            __syncthreads();
        }

        const unsigned thr = s.prefix;

        // tie-break: indices equal to threshold (all ties are in cand list)
        for (int i = tid; i < cnt; i += TPB) {
            unsigned key = (unsigned)(s.u.cand[i] >> 32) & 0x7fffffffu;
            if (key == thr) {
                int pos = atomicAdd(&s.eqCount, 1);
                if (pos < EQ_CAP) s.eqIdx[pos] = (int)(unsigned)s.u.cand[i];
            }
        }
        __syncthreads();
        if (tid == 0) {
            int e = s.eqCount; if (e > EQ_CAP) e = EQ_CAP;
            int m = s.r;       if (m > e) m = e;
            for (int a = 1; a < e; a++) {
                int v = s.eqIdx[a]; int bq = a - 1;
                while (bq >= 0 && s.eqIdx[bq] > v) { s.eqIdx[bq + 1] = s.eqIdx[bq]; bq--; }
                s.eqIdx[bq + 1] = v;
            }
            s.cutoff = (m > 0) ? s.eqIdx[m - 1] : -1;
        }
        __syncthreads();

        // output: zero-fill everything, then scatter winners (ordered by barrier)
        {
            float4 z = make_float4(0.f, 0.f, 0.f, 0.f);
#pragma unroll
            for (int i = 0; i < V4; i++) __stcs(&xout[i * TPB + tid], z);
        }
        __syncthreads();
        {
            const int cut = s.cutoff;
            for (int i = tid; i < cnt; i += TPB) {
                const unsigned long long rec = s.u.cand[i];
                const unsigned bits = (unsigned)(rec >> 32);
                const unsigned key  = bits & 0x7fffffffu;
                const int idx = (int)(unsigned)rec;
                if (key > thr || (key == thr && idx <= cut))
                    __stcs(&orow[idx], __uint_as_float(bits));
            }
        }
        return;
    }

    // ================= FALLBACK (rare; arbitrary inputs) =================
    if (tid == 0) { s.prefix = 0u; s.r = k; }
    unsigned* hw = s.u.hist[w];

#pragma unroll
    for (int lev = 0; lev < 4; lev++) {
        const int      shift = (lev == 0) ? 23 : (lev == 1) ? 15 : (lev == 2) ? 7 : 0;
        const int      hi    = (lev == 0) ? 31 : (lev == 1) ? 23 : (lev == 2) ? 15 : 7;
        const unsigned mask  = (lev == 3) ? 0x7fu : 0xffu;

        for (int i = tid; i < NW * 256; i += TPB) (&s.u.hist[0][0])[i] = 0u;
        __syncthreads();
        const unsigned pref_hi = s.prefix >> hi;
#pragma unroll
        for (int i = 0; i < V4; i++) {
            float4 v = xin[i * TPB + tid];
            unsigned bb[4]; bits_of(v, bb);
#pragma unroll
            for (int j = 0; j < 4; j++) {
                unsigned key = bb[j] & 0x7fffffffu;
                unsigned d = ((key >> hi) == pref_hi) ? ((key >> shift) & mask) : 0x100u;
                hist_add(hw, d);
            }
        }
        __syncthreads();
        if (tid < 256) {
            unsigned t = 0;
#pragma unroll
            for (int ww = 0; ww < NW; ww++) t += s.u.hist[ww][tid];
            s.tot[tid] = t;
        }
        __syncthreads();
        if (tid < 32) select_bin(&s, shift);
        __syncthreads();
    }

    const unsigned thr = s.prefix;
#pragma unroll
    for (int i = 0; i < V4; i++) {
        const int i4 = i * TPB + tid;
        float4 v = xin[i4];
        unsigned bb[4]; bits_of(v, bb);
#pragma unroll
        for (int j = 0; j < 4; j++) {
            if ((bb[j] & 0x7fffffffu) == thr) {
                int pos = atomicAdd(&s.eqCount, 1);
                if (pos < EQ_CAP) s.eqIdx[pos] = i4 * 4 + j;
            }
        }
    }
    __syncthreads();
    if (tid == 0) {
        int e = s.eqCount; if (e > EQ_CAP) e = EQ_CAP;
        int m = s.r;       if (m > e) m = e;
        for (int a = 1; a < e; a++) {
            int v = s.eqIdx[a]; int bq = a - 1;
            while (bq >= 0 && s.eqIdx[bq] > v) { s.eqIdx[bq + 1] = s.eqIdx[bq]; bq--; }
            s.eqIdx[bq + 1] = v;
        }
        s.cutoff = (m > 0) ? s.eqIdx[m - 1] : -1;
    }
    __syncthreads();
    const int cut = s.cutoff;
#pragma unroll
    for (int i = 0; i < V4; i++) {
        const int i4 = i * TPB + tid;
        const float4 v = xin[i4];
        unsigned bb[4]; bits_of(v, bb);
        const int e0 = i4 * 4;
        float4 o;
        unsigned k0 = bb[0] & 0x7fffffffu, k1 = bb[1] & 0x7fffffffu;
        unsigned k2 = bb[2] & 0x7fffffffu, k3 = bb[3] & 0x7fffffffu;
        o.x = (k0 > thr || (k0 == thr && (e0 + 0) <= cut)) ? v.x : 0.f;
        o.y = (k1 > thr || (k1 == thr && (e0 + 1) <= cut)) ? v.y : 0.f;
        o.z = (k2 > thr || (k2 == thr && (e0 + 2) <= cut)) ? v.z : 0.f;
        o.w = (k3 > thr || (k3 == thr && (e0 + 3) <= cut)) ? v.w : 0.f;
        __stcs(&xout[i4], o);
    }
}

extern "C" void kernel_launch(void* const* d_in, const int* in_sizes, int n_in,
                              void* d_out, int out_size)
{
    const float* x = (const float*)d_in[0];
    const int*   k = (const int*)d_in[1];
    float* out = (float*)d_out;
    const int rows = in_sizes[0] / COLS;

    topk_kernel<<<rows, TPB>>>(x, k, out);
}

// round 11
// speedup vs baseline: 2.2877x; 2.2877x over previous
#include <cuda_runtime.h>
#include <stdint.h>

#define COLS   16384
#define TPB    512
#define NW     (TPB / 32)
#define V4     (COLS / 4 / TPB)   // 8 float4 per thread
#define CAP    2048
#define EQ_CAP 128
#define T0 0x40800000u            // |x| >= 4  (exp >= 129)
#define T1 0x40000000u            // |x| >= 2  (exp >= 128)

struct __align__(16) SmemT {
    union {
        unsigned long long cand[CAP];     // fast path: (bits<<32)|idx
        unsigned           hist[NW][256]; // fallback: per-warp hists
    } u;                                  // 16 KB
    unsigned tot[256];
    unsigned wcnt[NW][2];
    int      eqIdx[EQ_CAP];
    unsigned prefix;
    int      r;
    int      eqCount;
    int      candCount;
    int      cutoff;
    int      fb;
};

__device__ __forceinline__ void hist_add(unsigned* h, unsigned d) {
    unsigned mm = __match_any_sync(0xffffffffu, d);
    if (d < 256u) {
        unsigned leader = __ffs(mm) - 1u;
        if ((threadIdx.x & 31u) == leader) h[d] += (unsigned)__popc(mm);
    }
}

// Warp 0: largest digit d with suffix_count(d) >= r; update prefix and r.
__device__ __forceinline__ void select_bin(SmemT* s, int shift) {
    const int lane = threadIdx.x & 31;
    const unsigned r = (unsigned)s->r;
    const unsigned base = (unsigned)lane * 8u;
    unsigned loc[8];
    unsigned sum = 0;
#pragma unroll
    for (int j = 7; j >= 0; j--) { sum += s->tot[base + j]; loc[j] = sum; }
    const unsigned lanesum = sum;
    unsigned acc = lanesum;
#pragma unroll
    for (int o = 1; o < 32; o <<= 1) {
        unsigned v = __shfl_down_sync(0xffffffffu, acc, o);
        if (lane < 32 - o) acc += v;
    }
    const unsigned above = acc - lanesum;
#pragma unroll
    for (int j = 0; j < 8; j++) {
        unsigned g     = above + loc[j];
        unsigned gnext = (j == 7) ? above : (above + loc[j+1]);
        if (g >= r && gnext < r) {
            s->prefix |= (base + (unsigned)j) << shift;
            s->r = (int)(r - gnext);
        }
    }
}

__device__ __forceinline__ void bits_of(float4 v, unsigned bb[4]) {
    bb[0] = __float_as_uint(v.x);
    bb[1] = __float_as_uint(v.y);
    bb[2] = __float_as_uint(v.z);
    bb[3] = __float_as_uint(v.w);
}

__global__ void __launch_bounds__(TPB, 3)
topk_kernel(const float* __restrict__ x, const int* __restrict__ kptr,
            float* __restrict__ out)
{
    __shared__ SmemT s;
    const int tid  = threadIdx.x;
    const int w    = tid >> 5;
    const int lane = tid & 31;
    const size_t rowoff = (size_t)blockIdx.x * COLS;
    const float4* __restrict__ xin  = reinterpret_cast<const float4*>(x + rowoff);
    float4* __restrict__       xout = reinterpret_cast<float4*>(out + rowoff);
    float* __restrict__        orow = out + rowoff;

    const int k = *kptr;
    if (k >= COLS) {
#pragma unroll
        for (int i = 0; i < V4; i++) __stcs(&xout[i*TPB + tid], __ldcs(&xin[i*TPB + tid]));
        return;
    }
    if (k <= 0) {
        float4 z = make_float4(0.f, 0.f, 0.f, 0.f);
#pragma unroll
        for (int i = 0; i < V4; i++) __stcs(&xout[i*TPB + tid], z);
        return;
    }

    if (tid == 0) { s.candCount = 0; s.eqCount = 0; }
    __syncthreads();

    // ========== pass 1: single gmem read, 2 threshold counters, rare append ==========
    unsigned c0 = 0, c1 = 0;
#pragma unroll
    for (int o = 0; o < 2; o++) {               // two 4-deep load batches (MLP>=4)
        float4 vv[4];
#pragma unroll
        for (int i = 0; i < 4; i++)
            vv[i] = __ldcs(&xin[(o * 4 + i) * TPB + tid]);
#pragma unroll
        for (int i = 0; i < 4; i++) {
            const int i4 = (o * 4 + i) * TPB + tid;
            unsigned bb[4]; bits_of(vv[i], bb);
#pragma unroll
            for (int j = 0; j < 4; j++) {
                unsigned key = bb[j] & 0x7fffffffu;
                c0 += (key >= T0);
                if (key >= T1) {                // ~4.5% of elements
                    c1++;
                    int pos = atomicAdd(&s.candCount, 1);
                    if (pos < CAP)
                        s.u.cand[pos] = ((unsigned long long)bb[j] << 32)
                                        | (unsigned)(i4 * 4 + j);
                }
            }
        }
    }
#pragma unroll
    for (int o = 16; o >= 1; o >>= 1) {
        c0 += __shfl_down_sync(0xffffffffu, c0, o);
        c1 += __shfl_down_sync(0xffffffffu, c1, o);
    }
    if (lane == 0) { s.wcnt[w][0] = c0; s.wcnt[w][1] = c1; }
    __syncthreads();

    if (tid == 0) {
        unsigned a0 = 0, a1 = 0;
#pragma unroll
        for (int ww = 0; ww < NW; ww++) { a0 += s.wcnt[ww][0]; a1 += s.wcnt[ww][1]; }
        bool fast = (a0 < (unsigned)k) && (a1 >= (unsigned)k) && (a1 <= CAP);
        s.fb = fast ? 0 : 1;
        s.prefix = T1;               // exp == 128 bin
        s.r = k - (int)a0;           // rank remaining inside/below that bin
    }
    __syncthreads();

    if (s.fb == 0) {
        // ========== FAST PATH: refine mantissa over candidate list ==========
        const int cnt = s.candCount;
#pragma unroll
        for (int lev = 1; lev < 4; lev++) {   // mantissa bits 22:15, 14:7, 6:0
            const int      shift = (lev == 1) ? 15 : (lev == 2) ? 7 : 0;
            const int      hi    = (lev == 1) ? 23 : (lev == 2) ? 15 : 7;
            const unsigned mask  = (lev == 3) ? 0x7fu : 0xffu;
            const unsigned pref_hi = s.prefix >> hi;

            if (tid < 256) s.tot[tid] = 0u;
            __syncthreads();
            for (int i = tid; i < cnt; i += TPB) {
                unsigned key = (unsigned)(s.u.cand[i] >> 32) & 0x7fffffffu;
                if ((key >> hi) == pref_hi)
                    atomicAdd(&s.tot[(key >> shift) & mask], 1u);
            }
            __syncthreads();
            if (tid < 32) select_bin(&s, shift);
            __syncthreads();
        }

        const unsigned thr = s.prefix;

        // tie-break: indices equal to threshold (all ties are in cand list)
        for (int i = tid; i < cnt; i += TPB) {
            unsigned key = (unsigned)(s.u.cand[i] >> 32) & 0x7fffffffu;
            if (key == thr) {
                int pos = atomicAdd(&s.eqCount, 1);
                if (pos < EQ_CAP) s.eqIdx[pos] = (int)(unsigned)s.u.cand[i];
            }
        }
        __syncthreads();
        if (tid == 0) {
            int e = s.eqCount; if (e > EQ_CAP) e = EQ_CAP;
            int m = s.r;       if (m > e) m = e;
            for (int a = 1; a < e; a++) {
                int v = s.eqIdx[a]; int bq = a - 1;
                while (bq >= 0 && s.eqIdx[bq] > v) { s.eqIdx[bq + 1] = s.eqIdx[bq]; bq--; }
                s.eqIdx[bq + 1] = v;
            }
            s.cutoff = (m > 0) ? s.eqIdx[m - 1] : -1;
        }
        __syncthreads();

        // output: zero-fill then scatter winners (ordered by barrier)
        {
            float4 z = make_float4(0.f, 0.f, 0.f, 0.f);
#pragma unroll
            for (int i = 0; i < V4; i++) __stcs(&xout[i * TPB + tid], z);
        }
        __syncthreads();
        {
            const int cut = s.cutoff;
            for (int i = tid; i < cnt; i += TPB) {
                const unsigned long long rec = s.u.cand[i];
                const unsigned bits = (unsigned)(rec >> 32);
                const unsigned key  = bits & 0x7fffffffu;
                const int idx = (int)(unsigned)rec;
                if (key > thr || (key == thr && idx <= cut))
                    __stcs(&orow[idx], __uint_as_float(bits));
            }
        }
        return;
    }

    // ========== FALLBACK (arbitrary inputs; exact full radix from gmem) ==========
    if (tid == 0) { s.prefix = 0u; s.r = k; }
    unsigned* hw = s.u.hist[w];

#pragma unroll
    for (int lev = 0; lev < 4; lev++) {
        const int      shift = (lev == 0) ? 23 : (lev == 1) ? 15 : (lev == 2) ? 7 : 0;
        const int      hi    = (lev == 0) ? 31 : (lev == 1) ? 23 : (lev == 2) ? 15 : 7;
        const unsigned mask  = (lev == 3) ? 0x7fu : 0xffu;

        for (int i = tid; i < NW * 256; i += TPB) (&s.u.hist[0][0])[i] = 0u;
        __syncthreads();
        const unsigned pref_hi = s.prefix >> hi;
#pragma unroll
        for (int i = 0; i < V4; i++) {
            float4 v = xin[i * TPB + tid];
            unsigned bb[4]; bits_of(v, bb);
#pragma unroll
            for (int j = 0; j < 4; j++) {
                unsigned key = bb[j] & 0x7fffffffu;
                unsigned d = ((key >> hi) == pref_hi) ? ((key >> shift) & mask) : 0x100u;
                hist_add(hw, d);
            }
        }
        __syncthreads();
        if (tid < 256) {
            unsigned t = 0;
#pragma unroll
            for (int ww = 0; ww < NW; ww++) t += s.u.hist[ww][tid];
            s.tot[tid] = t;
        }
        __syncthreads();
        if (tid < 32) select_bin(&s, shift);
        __syncthreads();
    }

    const unsigned thr = s.prefix;
#pragma unroll
    for (int i = 0; i < V4; i++) {
        const int i4 = i * TPB + tid;
        float4 v = xin[i4];
        unsigned bb[4]; bits_of(v, bb);
#pragma unroll
        for (int j = 0; j < 4; j++) {
            if ((bb[j] & 0x7fffffffu) == thr) {
                int pos = atomicAdd(&s.eqCount, 1);
                if (pos < EQ_CAP) s.eqIdx[pos] = i4 * 4 + j;
            }
        }
    }
    __syncthreads();
    if (tid == 0) {
        int e = s.eqCount; if (e > EQ_CAP) e = EQ_CAP;
        int m = s.r;       if (m > e) m = e;
        for (int a = 1; a < e; a++) {
            int v = s.eqIdx[a]; int bq = a - 1;
            while (bq >= 0 && s.eqIdx[bq] > v) { s.eqIdx[bq + 1] = s.eqIdx[bq]; bq--; }
            s.eqIdx[bq + 1] = v;
        }
        s.cutoff = (m > 0) ? s.eqIdx[m - 1] : -1;
    }
    __syncthreads();
    const int cut = s.cutoff;
#pragma unroll
    for (int i = 0; i < V4; i++) {
        const int i4 = i * TPB + tid;
        const float4 v = xin[i4];
        unsigned bb[4]; bits_of(v, bb);
        const int e0 = i4 * 4;
        float4 o;
        unsigned k0 = bb[0] & 0x7fffffffu, k1 = bb[1] & 0x7fffffffu;
        unsigned k2 = bb[2] & 0x7fffffffu, k3 = bb[3] & 0x7fffffffu;
        o.x = (k0 > thr || (k0 == thr && (e0 + 0) <= cut)) ? v.x : 0.f;
        o.y = (k1 > thr || (k1 == thr && (e0 + 1) <= cut)) ? v.y : 0.f;
        o.z = (k2 > thr || (k2 == thr && (e0 + 2) <= cut)) ? v.z : 0.f;
        o.w = (k3 > thr || (k3 == thr && (e0 + 3) <= cut)) ? v.w : 0.f;
        __stcs(&xout[i4], o);
    }
}

extern "C" void kernel_launch(void* const* d_in, const int* in_sizes, int n_in,
                              void* d_out, int out_size)
{
    const float* x = (const float*)d_in[0];
    const int*   k = (const int*)d_in[1];
    float* out = (float*)d_out;
    const int rows = in_sizes[0] / COLS;

    topk_kernel<<<rows, TPB>>>(x, k, out);
}

// round 12
// speedup vs baseline: 2.6048x; 1.1386x over previous
#include <cuda_runtime.h>
#include <stdint.h>

#define COLS   16384
#define TPB    512
#define NW     (TPB / 32)
#define V4     (COLS / 4 / TPB)   // 8 float4 per thread
#define CAP    2048
#define EQ_CAP 128
#define T0 0x40800000u            // |x| >= 4  (exp >= 129)
#define T1 0x40000000u            // |x| >= 2  (exp >= 128)

struct __align__(16) SmemT {
    union {
        unsigned long long cand[CAP];     // fast path: (bits<<32)|idx
        unsigned           hist[NW][256]; // fallback: per-warp hists
    } u;                                  // 16 KB
    unsigned tot[256];
    unsigned wcnt[NW];
    int      eqIdx[EQ_CAP];
    unsigned prefix;
    int      r;
    int      eqCount;
    int      candCount;
    int      cutoff;
    int      fb;
};

__device__ __forceinline__ void hist_add(unsigned* h, unsigned d) {
    unsigned mm = __match_any_sync(0xffffffffu, d);
    if (d < 256u) {
        unsigned leader = __ffs(mm) - 1u;
        if ((threadIdx.x & 31u) == leader) h[d] += (unsigned)__popc(mm);
    }
}

// Warp 0: largest digit d with suffix_count(d) >= r; update prefix and r.
__device__ __forceinline__ void select_bin(SmemT* s, int shift) {
    const int lane = threadIdx.x & 31;
    const unsigned r = (unsigned)s->r;
    const unsigned base = (unsigned)lane * 8u;
    unsigned loc[8];
    unsigned sum = 0;
#pragma unroll
    for (int j = 7; j >= 0; j--) { sum += s->tot[base + j]; loc[j] = sum; }
    const unsigned lanesum = sum;
    unsigned acc = lanesum;
#pragma unroll
    for (int o = 1; o < 32; o <<= 1) {
        unsigned v = __shfl_down_sync(0xffffffffu, acc, o);
        if (lane < 32 - o) acc += v;
    }
    const unsigned above = acc - lanesum;
#pragma unroll
    for (int j = 0; j < 8; j++) {
        unsigned g     = above + loc[j];
        unsigned gnext = (j == 7) ? above : (above + loc[j+1]);
        if (g >= r && gnext < r) {
            s->prefix |= (base + (unsigned)j) << shift;
            s->r = (int)(r - gnext);
        }
    }
}

__device__ __forceinline__ void bits_of(float4 v, unsigned bb[4]) {
    bb[0] = __float_as_uint(v.x);
    bb[1] = __float_as_uint(v.y);
    bb[2] = __float_as_uint(v.z);
    bb[3] = __float_as_uint(v.w);
}

__global__ void __launch_bounds__(TPB, 3)
topk_kernel(const float* __restrict__ x, const int* __restrict__ kptr,
            float* __restrict__ out)
{
    __shared__ SmemT s;
    const int tid  = threadIdx.x;
    const int w    = tid >> 5;
    const int lane = tid & 31;
    const size_t rowoff = (size_t)blockIdx.x * COLS;
    const float4* __restrict__ xin  = reinterpret_cast<const float4*>(x + rowoff);
    float4* __restrict__       xout = reinterpret_cast<float4*>(out + rowoff);
    float* __restrict__        orow = out + rowoff;

    const int k = *kptr;
    if (k >= COLS) {
#pragma unroll
        for (int i = 0; i < V4; i++) __stcs(&xout[i*TPB + tid], __ldcs(&xin[i*TPB + tid]));
        return;
    }
    if (k <= 0) {
        float4 z = make_float4(0.f, 0.f, 0.f, 0.f);
#pragma unroll
        for (int i = 0; i < V4; i++) __stcs(&xout[i*TPB + tid], z);
        return;
    }

    if (tid == 0) { s.candCount = 0; s.eqCount = 0; }
    __syncthreads();

    // ===== pass 1: single gmem read FUSED with zero-fill write =====
    // read + write streams both in flight from the start; candidates appended
    // via rare divergent shared atomic (~4.5% of elements).
    unsigned c0 = 0;
    const float4 z4 = make_float4(0.f, 0.f, 0.f, 0.f);
#pragma unroll
    for (int o = 0; o < 2; o++) {               // two 4-deep load batches (MLP>=4)
        float4 vv[4];
#pragma unroll
        for (int i = 0; i < 4; i++)
            vv[i] = __ldcs(&xin[(o * 4 + i) * TPB + tid]);
#pragma unroll
        for (int i = 0; i < 4; i++)             // fused zero-fill (independent)
            __stcs(&xout[(o * 4 + i) * TPB + tid], z4);
#pragma unroll
        for (int i = 0; i < 4; i++) {
            const int i4 = (o * 4 + i) * TPB + tid;
            unsigned bb[4]; bits_of(vv[i], bb);
#pragma unroll
            for (int j = 0; j < 4; j++) {
                unsigned key = bb[j] & 0x7fffffffu;
                c0 += (key >= T0);
                if (key >= T1) {
                    int pos = atomicAdd(&s.candCount, 1);
                    if (pos < CAP)
                        s.u.cand[pos] = ((unsigned long long)bb[j] << 32)
                                        | (unsigned)(i4 * 4 + j);
                }
            }
        }
    }
#pragma unroll
    for (int o = 16; o >= 1; o >>= 1)
        c0 += __shfl_down_sync(0xffffffffu, c0, o);
    if (lane == 0) s.wcnt[w] = c0;
    __syncthreads();

    if (tid == 0) {
        unsigned a0 = 0;
#pragma unroll
        for (int ww = 0; ww < NW; ww++) a0 += s.wcnt[ww];
        const unsigned a1 = (unsigned)s.candCount;     // all |x|>=2 elements
        bool fast = (a0 < (unsigned)k) && (a1 >= (unsigned)k) && (a1 <= CAP);
        s.fb = fast ? 0 : 1;
        s.prefix = T1;               // exp == 128 bin
        s.r = k - (int)a0;           // rank remaining inside/below that bin
    }
    __syncthreads();

    if (s.fb == 0) {
        // ===== FAST PATH: refine mantissa over candidate list =====
        const int cnt = s.candCount;
#pragma unroll
        for (int lev = 1; lev < 4; lev++) {   // mantissa bits 22:15, 14:7, 6:0
            const int      shift = (lev == 1) ? 15 : (lev == 2) ? 7 : 0;
            const int      hi    = (lev == 1) ? 23 : (lev == 2) ? 15 : 7;
            const unsigned mask  = (lev == 3) ? 0x7fu : 0xffu;
            const unsigned pref_hi = s.prefix >> hi;

            if (tid < 256) s.tot[tid] = 0u;
            __syncthreads();
            for (int i = tid; i < cnt; i += TPB) {
                unsigned key = (unsigned)(s.u.cand[i] >> 32) & 0x7fffffffu;
                if ((key >> hi) == pref_hi)
                    atomicAdd(&s.tot[(key >> shift) & mask], 1u);
            }
            __syncthreads();
            if (tid < 32) select_bin(&s, shift);
            __syncthreads();
        }

        const unsigned thr = s.prefix;

        // tie-break: indices equal to threshold (all ties are in cand list)
        for (int i = tid; i < cnt; i += TPB) {
            unsigned key = (unsigned)(s.u.cand[i] >> 32) & 0x7fffffffu;
            if (key == thr) {
                int pos = atomicAdd(&s.eqCount, 1);
                if (pos < EQ_CAP) s.eqIdx[pos] = (int)(unsigned)s.u.cand[i];
            }
        }
        __syncthreads();
        if (tid == 0) {
            int e = s.eqCount; if (e > EQ_CAP) e = EQ_CAP;
            int m = s.r;       if (m > e) m = e;
            for (int a = 1; a < e; a++) {
                int v = s.eqIdx[a]; int bq = a - 1;
                while (bq >= 0 && s.eqIdx[bq] > v) { s.eqIdx[bq + 1] = s.eqIdx[bq]; bq--; }
                s.eqIdx[bq + 1] = v;
            }
            s.cutoff = (m > 0) ? s.eqIdx[m - 1] : -1;
        }
        __syncthreads();   // also orders pass-1 zero stores before the scatter

        // scatter winners over the already-zeroed row
        {
            const int cut = s.cutoff;
            for (int i = tid; i < cnt; i += TPB) {
                const unsigned long long rec = s.u.cand[i];
                const unsigned bits = (unsigned)(rec >> 32);
                const unsigned key  = bits & 0x7fffffffu;
                const int idx = (int)(unsigned)rec;
                if (key > thr || (key == thr && idx <= cut))
                    __stcs(&orow[idx], __uint_as_float(bits));
            }
        }
        return;
    }

    // ===== FALLBACK (arbitrary inputs; exact full radix from gmem) =====
    if (tid == 0) { s.prefix = 0u; s.r = k; }
    unsigned* hw = s.u.hist[w];

#pragma unroll
    for (int lev = 0; lev < 4; lev++) {
        const int      shift = (lev == 0) ? 23 : (lev == 1) ? 15 : (lev == 2) ? 7 : 0;
        const int      hi    = (lev == 0) ? 31 : (lev == 1) ? 23 : (lev == 2) ? 15 : 7;
        const unsigned mask  = (lev == 3) ? 0x7fu : 0xffu;

        for (int i = tid; i < NW * 256; i += TPB) (&s.u.hist[0][0])[i] = 0u;
        __syncthreads();
        const unsigned pref_hi = s.prefix >> hi;
#pragma unroll
        for (int i = 0; i < V4; i++) {
            float4 v = xin[i * TPB + tid];
            unsigned bb[4]; bits_of(v, bb);
#pragma unroll
            for (int j = 0; j < 4; j++) {
                unsigned key = bb[j] & 0x7fffffffu;
                unsigned d = ((key >> hi) == pref_hi) ? ((key >> shift) & mask) : 0x100u;
                hist_add(hw, d);
            }
        }
        __syncthreads();
        if (tid < 256) {
            unsigned t = 0;
#pragma unroll
            for (int ww = 0; ww < NW; ww++) t += s.u.hist[ww][tid];
            s.tot[tid] = t;
        }
        __syncthreads();
        if (tid < 32) select_bin(&s, shift);
        __syncthreads();
    }

    const unsigned thr = s.prefix;
#pragma unroll
    for (int i = 0; i < V4; i++) {
        const int i4 = i * TPB + tid;
        float4 v = xin[i4];
        unsigned bb[4]; bits_of(v, bb);
#pragma unroll
        for (int j = 0; j < 4; j++) {
            if ((bb[j] & 0x7fffffffu) == thr) {
                int pos = atomicAdd(&s.eqCount, 1);
                if (pos < EQ_CAP) s.eqIdx[pos] = i4 * 4 + j;
            }
        }
    }
    __syncthreads();
    if (tid == 0) {
        int e = s.eqCount; if (e > EQ_CAP) e = EQ_CAP;
        int m = s.r;       if (m > e) m = e;
        for (int a = 1; a < e; a++) {
            int v = s.eqIdx[a]; int bq = a - 1;
            while (bq >= 0 && s.eqIdx[bq] > v) { s.eqIdx[bq + 1] = s.eqIdx[bq]; bq--; }
            s.eqIdx[bq + 1] = v;
        }
        s.cutoff = (m > 0) ? s.eqIdx[m - 1] : -1;
    }
    __syncthreads();
    const int cut = s.cutoff;
#pragma unroll
    for (int i = 0; i < V4; i++) {
        const int i4 = i * TPB + tid;
        const float4 v = xin[i4];
        unsigned bb[4]; bits_of(v, bb);
        const int e0 = i4 * 4;
        float4 o;
        unsigned k0 = bb[0] & 0x7fffffffu, k1 = bb[1] & 0x7fffffffu;
        unsigned k2 = bb[2] & 0x7fffffffu, k3 = bb[3] & 0x7fffffffu;
        o.x = (k0 > thr || (k0 == thr && (e0 + 0) <= cut)) ? v.x : 0.f;
        o.y = (k1 > thr || (k1 == thr && (e0 + 1) <= cut)) ? v.y : 0.f;
        o.z = (k2 > thr || (k2 == thr && (e0 + 2) <= cut)) ? v.z : 0.f;
        o.w = (k3 > thr || (k3 == thr && (e0 + 3) <= cut)) ? v.w : 0.f;
        __stcs(&xout[i4], o);
    }
}

extern "C" void kernel_launch(void* const* d_in, const int* in_sizes, int n_in,
                              void* d_out, int out_size)
{
    const float* x = (const float*)d_in[0];
    const int*   k = (const int*)d_in[1];
    float* out = (float*)d_out;
    const int rows = in_sizes[0] / COLS;

    topk_kernel<<<rows, TPB>>>(x, k, out);
}

// round 14
// speedup vs baseline: 2.7900x; 1.0711x over previous
#include <cuda_runtime.h>
#include <stdint.h>

#define COLS   16384
#define TPB    256
#define NW     (TPB / 32)
#define V4     (COLS / 4 / TPB)   // 16 float4 per thread
#define CAP    2048
#define EQ_CAP 128
#define T0 0x40800000u            // |x| >= 4  (exp >= 129)
#define T1 0x40000000u            // |x| >= 2  (exp >= 128)

struct __align__(16) SmemT {
    union {
        unsigned long long cand[CAP];     // fast path: (bits<<32)|idx
        unsigned           hist[NW][256]; // fallback: per-warp hists
    } u;                                  // 16 KB
    unsigned tot[256];
    unsigned wcnt[NW];
    int      eqIdx[EQ_CAP];
    unsigned prefix;
    int      r;
    int      eqCount;
    int      candCount;
    int      cutoff;
    int      fb;
};

__device__ __forceinline__ void hist_add(unsigned* h, unsigned d) {
    unsigned mm = __match_any_sync(0xffffffffu, d);
    if (d < 256u) {
        unsigned leader = __ffs(mm) - 1u;
        if ((threadIdx.x & 31u) == leader) h[d] += (unsigned)__popc(mm);
    }
}

// Warp 0: largest digit d with suffix_count(d) >= r; update prefix and r.
__device__ __forceinline__ void select_bin(SmemT* s, int shift) {
    const int lane = threadIdx.x & 31;
    const unsigned r = (unsigned)s->r;
    const unsigned base = (unsigned)lane * 8u;
    unsigned loc[8];
    unsigned sum = 0;
#pragma unroll
    for (int j = 7; j >= 0; j--) { sum += s->tot[base + j]; loc[j] = sum; }
    const unsigned lanesum = sum;
    unsigned acc = lanesum;
#pragma unroll
    for (int o = 1; o < 32; o <<= 1) {
        unsigned v = __shfl_down_sync(0xffffffffu, acc, o);
        if (lane < 32 - o) acc += v;
    }
    const unsigned above = acc - lanesum;
#pragma unroll
    for (int j = 0; j < 8; j++) {
        unsigned g     = above + loc[j];
        unsigned gnext = (j == 7) ? above : (above + loc[j+1]);
        if (g >= r && gnext < r) {
            s->prefix |= (base + (unsigned)j) << shift;
            s->r = (int)(r - gnext);
        }
    }
}

__device__ __forceinline__ void bits_of(float4 v, unsigned bb[4]) {
    bb[0] = __float_as_uint(v.x);
    bb[1] = __float_as_uint(v.y);
    bb[2] = __float_as_uint(v.z);
    bb[3] = __float_as_uint(v.w);
}

__global__ void __launch_bounds__(TPB, 6)
topk_kernel(const float* __restrict__ x, const int* __restrict__ kptr,
            float* __restrict__ out)
{
    __shared__ SmemT s;
    const int tid  = threadIdx.x;
    const int w    = tid >> 5;
    const int lane = tid & 31;
    const size_t rowoff = (size_t)blockIdx.x * COLS;
    const float4* __restrict__ xin  = reinterpret_cast<const float4*>(x + rowoff);
    float4* __restrict__       xout = reinterpret_cast<float4*>(out + rowoff);
    float* __restrict__        orow = out + rowoff;

    const int k = *kptr;
    if (k >= COLS) {
#pragma unroll
        for (int i = 0; i < V4; i++) __stcs(&xout[i*TPB + tid], __ldcs(&xin[i*TPB + tid]));
        return;
    }
    if (k <= 0) {
        float4 z = make_float4(0.f, 0.f, 0.f, 0.f);
#pragma unroll
        for (int i = 0; i < V4; i++) __stcs(&xout[i*TPB + tid], z);
        return;
    }

    if (tid == 0) { s.candCount = 0; s.eqCount = 0; }
    __syncthreads();

    // ===== pass 1: single gmem read FUSED with zero-fill write =====
    unsigned c0 = 0;
    const float4 z4 = make_float4(0.f, 0.f, 0.f, 0.f);
#pragma unroll
    for (int o = 0; o < V4 / 4; o++) {          // 4-deep load batches (MLP>=4)
        float4 vv[4];
#pragma unroll
        for (int i = 0; i < 4; i++)
            vv[i] = __ldcs(&xin[(o * 4 + i) * TPB + tid]);
#pragma unroll
        for (int i = 0; i < 4; i++)             // fused zero-fill (independent)
            __stcs(&xout[(o * 4 + i) * TPB + tid], z4);
#pragma unroll
        for (int i = 0; i < 4; i++) {
            const int i4 = (o * 4 + i) * TPB + tid;
            unsigned bb[4]; bits_of(vv[i], bb);
#pragma unroll
            for (int j = 0; j < 4; j++) {
                unsigned key = bb[j] & 0x7fffffffu;
                c0 += (key >= T0);
                if (key >= T1) {                // ~4.5% of elements
                    int pos = atomicAdd(&s.candCount, 1);
                    if (pos < CAP)
                        s.u.cand[pos] = ((unsigned long long)bb[j] << 32)
                                        | (unsigned)(i4 * 4 + j);
                }
            }
        }
    }
#pragma unroll
    for (int o = 16; o >= 1; o >>= 1)
        c0 += __shfl_down_sync(0xffffffffu, c0, o);
    if (lane == 0) s.wcnt[w] = c0;
    __syncthreads();

    if (tid == 0) {
        unsigned a0 = 0;
#pragma unroll
        for (int ww = 0; ww < NW; ww++) a0 += s.wcnt[ww];
        const unsigned a1 = (unsigned)s.candCount;     // all |x|>=2 elements
        bool fast = (a0 < (unsigned)k) && (a1 >= (unsigned)k) && (a1 <= CAP);
        s.fb = fast ? 0 : 1;
        s.prefix = T1;               // exp == 128 bin
        s.r = k - (int)a0;           // rank remaining inside/below that bin
    }
    __syncthreads();

    if (s.fb == 0) {
        // ===== FAST PATH: refine mantissa over candidate list =====
        const int cnt = s.candCount;
#pragma unroll
        for (int lev = 1; lev < 4; lev++) {   // mantissa bits 22:15, 14:7, 6:0
            const int      shift = (lev == 1) ? 15 : (lev == 2) ? 7 : 0;
            const int      hi    = (lev == 1) ? 23 : (lev == 2) ? 15 : 7;
            const unsigned mask  = (lev == 3) ? 0x7fu : 0xffu;
            const unsigned pref_hi = s.prefix >> hi;

            s.tot[tid] = 0u;                  // TPB==256: all bins zeroed
            __syncthreads();
            for (int i = tid; i < cnt; i += TPB) {
                unsigned key = (unsigned)(s.u.cand[i] >> 32) & 0x7fffffffu;
                if ((key >> hi) == pref_hi)
                    atomicAdd(&s.tot[(key >> shift) & mask], 1u);
            }
            __syncthreads();
            if (tid < 32) select_bin(&s, shift);
            __syncthreads();
        }

        const unsigned thr = s.prefix;

        // tie-break: indices equal to threshold (all ties are in cand list)
        for (int i = tid; i < cnt; i += TPB) {
            unsigned key = (unsigned)(s.u.cand[i] >> 32) & 0x7fffffffu;
            if (key == thr) {
                int pos = atomicAdd(&s.eqCount, 1);
                if (pos < EQ_CAP) s.eqIdx[pos] = (int)(unsigned)s.u.cand[i];
            }
        }
        __syncthreads();
        if (tid == 0) {
            int e = s.eqCount; if (e > EQ_CAP) e = EQ_CAP;
            int m = s.r;       if (m > e) m = e;
            for (int a = 1; a < e; a++) {
                int v = s.eqIdx[a]; int bq = a - 1;
                while (bq >= 0 && s.eqIdx[bq] > v) { s.eqIdx[bq + 1] = s.eqIdx[bq]; bq--; }
                s.eqIdx[bq + 1] = v;
            }
            s.cutoff = (m > 0) ? s.eqIdx[m - 1] : -1;
        }
        __syncthreads();   // also orders pass-1 zero stores before the scatter

        // scatter winners over the already-zeroed row
        {
            const int cut = s.cutoff;
            for (int i = tid; i < cnt; i += TPB) {
                const unsigned long long rec = s.u.cand[i];
                const unsigned bits = (unsigned)(rec >> 32);
                const unsigned key  = bits & 0x7fffffffu;
                const int idx = (int)(unsigned)rec;
                if (key > thr || (key == thr && idx <= cut))
                    __stcs(&orow[idx], __uint_as_float(bits));
            }
        }
        return;
    }

    // ===== FALLBACK (arbitrary inputs; exact full radix from gmem) =====
    if (tid == 0) { s.prefix = 0u; s.r = k; }
    unsigned* hw = s.u.hist[w];

#pragma unroll
    for (int lev = 0; lev < 4; lev++) {
        const int      shift = (lev == 0) ? 23 : (lev == 1) ? 15 : (lev == 2) ? 7 : 0;
        const int      hi    = (lev == 0) ? 31 : (lev == 1) ? 23 : (lev == 2) ? 15 : 7;
        const unsigned mask  = (lev == 3) ? 0x7fu : 0xffu;

        for (int i = tid; i < NW * 256; i += TPB) (&s.u.hist[0][0])[i] = 0u;
        __syncthreads();
        const unsigned pref_hi = s.prefix >> hi;
#pragma unroll
        for (int i = 0; i < V4; i++) {
            float4 v = xin[i * TPB + tid];
            unsigned bb[4]; bits_of(v, bb);
#pragma unroll
            for (int j = 0; j < 4; j++) {
                unsigned key = bb[j] & 0x7fffffffu;
                unsigned d = ((key >> hi) == pref_hi) ? ((key >> shift) & mask) : 0x100u;
                hist_add(hw, d);
            }
        }
        __syncthreads();
        if (tid < 256) {
            unsigned t = 0;
#pragma unroll
            for (int ww = 0; ww < NW; ww++) t += s.u.hist[ww][tid];
            s.tot[tid] = t;
        }
        __syncthreads();
        if (tid < 32) select_bin(&s, shift);
        __syncthreads();
    }

    const unsigned thr = s.prefix;
#pragma unroll
    for (int i = 0; i < V4; i++) {
        const int i4 = i * TPB + tid;
        float4 v = xin[i4];
        unsigned bb[4]; bits_of(v, bb);
#pragma unroll
        for (int j = 0; j < 4; j++) {
            if ((bb[j] & 0x7fffffffu) == thr) {
                int pos = atomicAdd(&s.eqCount, 1);
                if (pos < EQ_CAP) s.eqIdx[pos] = i4 * 4 + j;
            }
        }
    }
    __syncthreads();
    if (tid == 0) {
        int e = s.eqCount; if (e > EQ_CAP) e = EQ_CAP;
        int m = s.r;       if (m > e) m = e;
        for (int a = 1; a < e; a++) {
            int v = s.eqIdx[a]; int bq = a - 1;
            while (bq >= 0 && s.eqIdx[bq] > v) { s.eqIdx[bq + 1] = s.eqIdx[bq]; bq--; }
            s.eqIdx[bq + 1] = v;
        }
        s.cutoff = (m > 0) ? s.eqIdx[m - 1] : -1;
    }
    __syncthreads();
    const int cut = s.cutoff;
#pragma unroll
    for (int i = 0; i < V4; i++) {
        const int i4 = i * TPB + tid;
        const float4 v = xin[i4];
        unsigned bb[4]; bits_of(v, bb);
        const int e0 = i4 * 4;
        float4 o;
        unsigned k0 = bb[0] & 0x7fffffffu, k1 = bb[1] & 0x7fffffffu;
        unsigned k2 = bb[2] & 0x7fffffffu, k3 = bb[3] & 0x7fffffffu;
        o.x = (k0 > thr || (k0 == thr && (e0 + 0) <= cut)) ? v.x : 0.f;
        o.y = (k1 > thr || (k1 == thr && (e0 + 1) <= cut)) ? v.y : 0.f;
        o.z = (k2 > thr || (k2 == thr && (e0 + 2) <= cut)) ? v.z : 0.f;
        o.w = (k3 > thr || (k3 == thr && (e0 + 3) <= cut)) ? v.w : 0.f;
        __stcs(&xout[i4], o);
    }
}

extern "C" void kernel_launch(void* const* d_in, const int* in_sizes, int n_in,
                              void* d_out, int out_size)
{
    const float* x = (const float*)d_in[0];
    const int*   k = (const int*)d_in[1];
    float* out = (float*)d_out;
    const int rows = in_sizes[0] / COLS;

    topk_kernel<<<rows, TPB>>>(x, k, out);
}